// round 1
// baseline (speedup 1.0000x reference)
#include <cuda_runtime.h>
#include <cstdint>

// Problem constants
#define BATCH_SEQ 640          // B*S = 32*20
#define NNODE     128
#define FDIM      64
#define NHEADS    4
#define NHID      64
#define OCOLS     256          // NHEADS*NHID
#define THREADS   512
#define ADJ_THR   0.05f

typedef unsigned long long ull;

// ---- packed f32x2 helpers (FFMA2 — ptxas never auto-fuses; PTX-only path) ----
__device__ __forceinline__ void fma2(ull& d, ull a, ull b) {
    asm("fma.rn.f32x2 %0, %1, %2, %0;" : "+l"(d) : "l"(a), "l"(b));
}
__device__ __forceinline__ ull pack2(float x, float y) {
    ull r; asm("mov.b64 %0, {%1, %2};" : "=l"(r) : "f"(x), "f"(y)); return r;
}
__device__ __forceinline__ float2 unpack2(ull v) {
    float2 f; asm("mov.b64 {%0, %1}, %2;" : "=f"(f.x), "=f"(f.y) : "l"(v)); return f;
}

// Shared memory layout (floats):
//   ht    [128][256]            @ 0       (32768)
//   union @ 32768:
//     phase1: W_s [64][256]               (16384)
//     phase2: attn [128][132]             (16896)
//   src_s [4][128]              @ 49664   (512)
//   tgt_s [4][128]              @ 50176   (512)
//   inv_s [128]                 @ 50688   (128)
//   maskb [512] (uint32)        @ 50816   (512)
// total floats = 51328 -> 205312 bytes
#define SMEM_FLOATS 51328
#define HT_OFF      0
#define SCR_OFF     32768
#define SRC_OFF     49664
#define TGT_OFF     50176
#define INV_OFF     50688
#define MSK_OFF     50816

extern __shared__ float smem[];

__global__ __launch_bounds__(THREADS, 1)
void gat_fused_kernel(const float* __restrict__ hg,
                      const float* __restrict__ adjg,
                      const float* __restrict__ Wg,
                      const float* __restrict__ ag,
                      float* __restrict__ outg)
{
    float* ht    = smem + HT_OFF;
    float* Ws    = smem + SCR_OFF;       // phase 1
    float* attn  = smem + SCR_OFF;       // phase 2 (union)
    float* src_s = smem + SRC_OFF;
    float* tgt_s = smem + TGT_OFF;
    float* inv_s = smem + INV_OFF;
    unsigned* maskb = (unsigned*)(smem + MSK_OFF);

    const int tid  = threadIdx.x;
    const int lane = tid & 31;
    const int wid  = tid >> 5;
    const int bs   = blockIdx.x;

    const float* hb   = hg   + (size_t)bs * NNODE * FDIM;
    const float* adjb = adjg + (size_t)bs * NNODE * NNODE;
    float*       outb = outg + (size_t)bs * NNODE * NHID;

    // ---------------- Load W into smem (coalesced float4) ----------------
    {
        const float4* Wg4 = (const float4*)Wg;
        float4* Ws4 = (float4*)Ws;
        #pragma unroll
        for (int i = 0; i < 8; i++)
            Ws4[tid + i * 512] = Wg4[tid + i * 512];
    }

    // ---------------- Adjacency -> bitmask (2KB), bit set == masked ----------------
    {
        #pragma unroll
        for (int it = 0; it < 32; it++) {
            int idx = it * 512 + tid;
            unsigned bal = __ballot_sync(0xffffffffu, adjb[idx] < ADJ_THR);
            if (lane == 0) maskb[idx >> 5] = bal;
        }
    }
    __syncthreads();

    // ---------------- GEMM1: ht[128][256] = h[128][64] @ W[64][256] ----------------
    // Thread tile: 8 rows x 8 cols. Warp lanes sweep columns (conflict-free ht writes).
    {
        const int tx   = tid & 31;            // 32 col groups
        const int ty   = tid >> 5;            // 16 row groups
        const int col0 = tx * 8;
        const int row0 = ty * 8;
        const int head = tx >> 3;             // 8 col-groups per head

        ull acc[8][4];
        #pragma unroll
        for (int r = 0; r < 8; r++)
            #pragma unroll
            for (int p = 0; p < 4; p++) acc[r][p] = pack2(0.f, 0.f);

        #pragma unroll 1
        for (int kq = 0; kq < 16; kq++) {
            float4 a4[8];
            #pragma unroll
            for (int r = 0; r < 8; r++)
                a4[r] = *(const float4*)&hb[(row0 + r) * FDIM + kq * 4];

            #pragma unroll
            for (int kk = 0; kk < 4; kk++) {
                const int k = kq * 4 + kk;
                const ulonglong2* bp = (const ulonglong2*)&Ws[k * OCOLS + col0];
                ulonglong2 b0 = bp[0];
                ulonglong2 b1 = bp[1];
                #pragma unroll
                for (int r = 0; r < 8; r++) {
                    float av = ((const float*)&a4[r])[kk];
                    ull a2 = pack2(av, av);
                    fma2(acc[r][0], a2, b0.x);
                    fma2(acc[r][1], a2, b0.y);
                    fma2(acc[r][2], a2, b1.x);
                    fma2(acc[r][3], a2, b1.y);
                }
            }
        }

        // Store ht (vectorized, conflict-free: lanes contiguous in columns)
        #pragma unroll
        for (int r = 0; r < 8; r++) {
            ulonglong2 v01; v01.x = acc[r][0]; v01.y = acc[r][1];
            ulonglong2 v23; v23.x = acc[r][2]; v23.y = acc[r][3];
            *(ulonglong2*)&ht[(row0 + r) * OCOLS + col0]     = v01;
            *(ulonglong2*)&ht[(row0 + r) * OCOLS + col0 + 4] = v23;
        }

        // Epilogue: src/tgt partial dots from register tile, 8-lane shfl reduce
        const int d0 = col0 & 63;
        float asrc[8], atgt[8];
        #pragma unroll
        for (int j = 0; j < 8; j++) {
            asrc[j] = ag[head * 128 + d0 + j];
            atgt[j] = ag[head * 128 + 64 + d0 + j];
        }
        #pragma unroll
        for (int r = 0; r < 8; r++) {
            float s = 0.f, t = 0.f;
            #pragma unroll
            for (int p = 0; p < 4; p++) {
                float2 c = unpack2(acc[r][p]);
                s += c.x * asrc[2 * p] + c.y * asrc[2 * p + 1];
                t += c.x * atgt[2 * p] + c.y * atgt[2 * p + 1];
            }
            // reduce across the 8 lanes sharing this (head, row)
            #pragma unroll
            for (int m = 4; m >= 1; m >>= 1) {
                s += __shfl_xor_sync(0xffffffffu, s, m);
                t += __shfl_xor_sync(0xffffffffu, t, m);
            }
            if ((tx & 7) == 0) {
                src_s[head * 128 + row0 + r] = s;
                tgt_s[head * 128 + row0 + r] = t;
            }
        }
    }
    __syncthreads();

    // ---------------- Per-head: e/softmax-numerator + GEMM2 accumulation ----------------
    const int tx2 = tid & 15;                 // 16 col groups of 4
    const int ty2 = tid >> 4;                 // 32 row groups of 4
    const int oc0 = tx2 * 4;
    const int or0 = ty2 * 4;

    ull oacc[4][2];
    #pragma unroll
    for (int r = 0; r < 4; r++) { oacc[r][0] = pack2(0.f, 0.f); oacc[r][1] = pack2(0.f, 0.f); }

    #pragma unroll 1
    for (int h = 0; h < NHEADS; h++) {
        // e-phase: warp w handles rows w*8 .. w*8+7, lanes sweep j
        {
            const float* srch = src_s + h * 128;
            const float* tgth = tgt_s + h * 128;
            #pragma unroll 1
            for (int rr = 0; rr < 8; rr++) {
                const int i = wid * 8 + rr;
                const float si = srch[i];
                float rs = 0.f;
                #pragma unroll
                for (int jj = 0; jj < 4; jj++) {
                    const int j = jj * 32 + lane;
                    float x = si + tgth[j];
                    float u = __expf(-x);
                    float sg = __fdividef(1.0f, 1.0f + u);
                    float p = __expf(sg);
                    if ((maskb[i * 4 + jj] >> lane) & 1u) p = 0.0f;
                    attn[i * 132 + j] = p;
                    rs += p;
                }
                #pragma unroll
                for (int m = 16; m >= 1; m >>= 1)
                    rs += __shfl_xor_sync(0xffffffffu, rs, m);
                if (lane == 0) inv_s[i] = __fdividef(1.0f, rs);
            }
        }
        __syncthreads();

        // GEMM2: th[128][64] = attn[128][128] @ ht[:, h*64:(h+1)*64]
        {
            ull th[4][2];
            #pragma unroll
            for (int r = 0; r < 4; r++) { th[r][0] = pack2(0.f, 0.f); th[r][1] = pack2(0.f, 0.f); }

            #pragma unroll 1
            for (int jq = 0; jq < 32; jq++) {
                float4 aq[4];
                #pragma unroll
                for (int r = 0; r < 4; r++)
                    aq[r] = *(const float4*)&attn[(or0 + r) * 132 + jq * 4];
                #pragma unroll
                for (int jj = 0; jj < 4; jj++) {
                    const int j = jq * 4 + jj;
                    ulonglong2 b = *(const ulonglong2*)&ht[j * OCOLS + h * 64 + oc0];
                    #pragma unroll
                    for (int r = 0; r < 4; r++) {
                        float av = ((const float*)&aq[r])[jj];
                        ull a2 = pack2(av, av);
                        fma2(th[r][0], a2, b.x);
                        fma2(th[r][1], a2, b.y);
                    }
                }
            }

            // scale by 1/rowsum and accumulate across heads
            #pragma unroll
            for (int r = 0; r < 4; r++) {
                float iv = inv_s[or0 + r];
                ull iv2 = pack2(iv, iv);
                fma2(oacc[r][0], iv2, th[r][0]);
                fma2(oacc[r][1], iv2, th[r][1]);
            }
        }
        __syncthreads();   // attn/inv_s reused next head
    }

    // ---------------- Write output: mean over heads ----------------
    #pragma unroll
    for (int r = 0; r < 4; r++) {
        float2 p0 = unpack2(oacc[r][0]);
        float2 p1 = unpack2(oacc[r][1]);
        float4 v;
        v.x = p0.x * 0.25f; v.y = p0.y * 0.25f;
        v.z = p1.x * 0.25f; v.w = p1.y * 0.25f;
        *(float4*)&outb[(or0 + r) * NHID + oc0] = v;
    }
}

extern "C" void kernel_launch(void* const* d_in, const int* in_sizes, int n_in,
                              void* d_out, int out_size)
{
    const float* h   = (const float*)d_in[0];
    const float* adj = (const float*)d_in[1];
    const float* W   = (const float*)d_in[2];
    const float* a   = (const float*)d_in[3];
    float* out = (float*)d_out;

    static bool attr_set = false;
    if (!attr_set) {
        cudaFuncSetAttribute(gat_fused_kernel,
                             cudaFuncAttributeMaxDynamicSharedMemorySize,
                             SMEM_FLOATS * sizeof(float));
        attr_set = true;
    }

    gat_fused_kernel<<<BATCH_SEQ, THREADS, SMEM_FLOATS * sizeof(float)>>>(h, adj, W, a, out);
}

// round 2
// speedup vs baseline: 1.0156x; 1.0156x over previous
#include <cuda_runtime.h>
#include <cstdint>

// Problem constants
#define BATCH_SEQ 640          // B*S = 32*20
#define NNODE     128
#define FDIM      64
#define NHEADS    4
#define NHID      64
#define OCOLS     256          // NHEADS*NHID
#define THREADS   512
#define ADJ_THR   0.05f

typedef unsigned long long ull;

// ---- packed f32x2 helpers (FFMA2 — ptxas never auto-fuses; PTX-only path) ----
__device__ __forceinline__ void fma2(ull& d, ull a, ull b) {
    asm("fma.rn.f32x2 %0, %1, %2, %0;" : "+l"(d) : "l"(a), "l"(b));
}
__device__ __forceinline__ ull pack2(float x, float y) {
    ull r; asm("mov.b64 %0, {%1, %2};" : "=l"(r) : "f"(x), "f"(y)); return r;
}
__device__ __forceinline__ float2 unpack2(ull v) {
    float2 f; asm("mov.b64 {%0, %1}, %2;" : "=f"(f.x), "=f"(f.y) : "l"(v)); return f;
}

// Shared memory layout (floats):
//   ht    [128][256]            @ 0       (32768)
//   union @ 32768:
//     phase1: W_s [64][256]               (16384)
//     phase2: attn [128][132]             (16896)
//   src_s [4][128]              @ 49664   (512)
//   tgt_s [4][128]              @ 50176   (512)
//   inv_s [128]                 @ 50688   (128)
//   maskb [512] (uint32)        @ 50816   (512)
// total floats = 51328 -> 205312 bytes
#define SMEM_FLOATS 51328
#define HT_OFF      0
#define SCR_OFF     32768
#define SRC_OFF     49664
#define TGT_OFF     50176
#define INV_OFF     50688
#define MSK_OFF     50816

extern __shared__ float smem[];

__global__ __launch_bounds__(THREADS, 1)
void gat_fused_kernel(const float* __restrict__ hg,
                      const float* __restrict__ adjg,
                      const float* __restrict__ Wg,
                      const float* __restrict__ ag,
                      float* __restrict__ outg)
{
    float* ht    = smem + HT_OFF;
    float* Ws    = smem + SCR_OFF;       // phase 1
    float* attn  = smem + SCR_OFF;       // phase 2 (union)
    float* src_s = smem + SRC_OFF;
    float* tgt_s = smem + TGT_OFF;
    float* inv_s = smem + INV_OFF;
    unsigned* maskb = (unsigned*)(smem + MSK_OFF);

    const int tid  = threadIdx.x;
    const int lane = tid & 31;
    const int wid  = tid >> 5;
    const int bs   = blockIdx.x;

    const float* hb   = hg   + (size_t)bs * NNODE * FDIM;
    const float* adjb = adjg + (size_t)bs * NNODE * NNODE;
    float*       outb = outg + (size_t)bs * NNODE * NHID;

    // ---------------- Load W into smem (coalesced float4) ----------------
    {
        const float4* Wg4 = (const float4*)Wg;
        float4* Ws4 = (float4*)Ws;
        #pragma unroll
        for (int i = 0; i < 8; i++)
            Ws4[tid + i * 512] = Wg4[tid + i * 512];
    }

    // ---------------- Adjacency -> bitmask (2KB), bit set == masked ----------------
    {
        #pragma unroll
        for (int it = 0; it < 32; it++) {
            int idx = it * 512 + tid;
            unsigned bal = __ballot_sync(0xffffffffu, adjb[idx] < ADJ_THR);
            if (lane == 0) maskb[idx >> 5] = bal;
        }
    }
    __syncthreads();

    // ---------------- GEMM1: ht[128][256] = h[128][64] @ W[64][256] ----------------
    // Warp tile 32 rows x 64 cols (4 row-bands x 4 col-bands; col-band == head).
    // Lane grid 4 row-groups x 8 col-groups; lane tile 8x8.
    // Per warp per k: only 256B of W traffic (its own 64-col band) -> crossbar
    // pressure 4x below FFMA2 issue cost.
    {
        const int br   = (wid & 3) * 32;         // row band
        const int head = wid >> 2;               // col band == head
        const int rg   = (lane >> 3) * 8;        // row group within band
        const int cg   = (lane & 7) * 8;         // col group within band
        const int row0 = br + rg;
        const int col0 = head * 64 + cg;

        ull acc[8][4];
        #pragma unroll
        for (int r = 0; r < 8; r++)
            #pragma unroll
            for (int p = 0; p < 4; p++) acc[r][p] = pack2(0.f, 0.f);

        #pragma unroll 1
        for (int kq = 0; kq < 16; kq++) {
            float4 a4[8];
            #pragma unroll
            for (int r = 0; r < 8; r++)
                a4[r] = *(const float4*)&hb[(row0 + r) * FDIM + kq * 4];

            #pragma unroll
            for (int kk = 0; kk < 4; kk++) {
                const int k = kq * 4 + kk;
                const ulonglong2* bp = (const ulonglong2*)&Ws[k * OCOLS + col0];
                ulonglong2 b0 = bp[0];
                ulonglong2 b1 = bp[1];
                #pragma unroll
                for (int r = 0; r < 8; r++) {
                    float av = ((const float*)&a4[r])[kk];
                    ull a2 = pack2(av, av);
                    fma2(acc[r][0], a2, b0.x);
                    fma2(acc[r][1], a2, b0.y);
                    fma2(acc[r][2], a2, b1.x);
                    fma2(acc[r][3], a2, b1.y);
                }
            }
        }

        // Store ht
        #pragma unroll
        for (int r = 0; r < 8; r++) {
            ulonglong2 v01; v01.x = acc[r][0]; v01.y = acc[r][1];
            ulonglong2 v23; v23.x = acc[r][2]; v23.y = acc[r][3];
            *(ulonglong2*)&ht[(row0 + r) * OCOLS + col0]     = v01;
            *(ulonglong2*)&ht[(row0 + r) * OCOLS + col0 + 4] = v23;
        }

        // Epilogue: src/tgt partial dots from register tile; reduce over the
        // 8 col-group lanes sharing the same row group (xor over lane&7).
        float asrc[8], atgt[8];
        #pragma unroll
        for (int j = 0; j < 8; j++) {
            asrc[j] = ag[head * 128 + cg + j];
            atgt[j] = ag[head * 128 + 64 + cg + j];
        }
        #pragma unroll
        for (int r = 0; r < 8; r++) {
            float s = 0.f, t = 0.f;
            #pragma unroll
            for (int p = 0; p < 4; p++) {
                float2 c = unpack2(acc[r][p]);
                s += c.x * asrc[2 * p] + c.y * asrc[2 * p + 1];
                t += c.x * atgt[2 * p] + c.y * atgt[2 * p + 1];
            }
            #pragma unroll
            for (int m = 4; m >= 1; m >>= 1) {
                s += __shfl_xor_sync(0xffffffffu, s, m);
                t += __shfl_xor_sync(0xffffffffu, t, m);
            }
            if ((lane & 7) == 0) {
                src_s[head * 128 + row0 + r] = s;
                tgt_s[head * 128 + row0 + r] = t;
            }
        }
    }
    __syncthreads();

    // ---------------- Per-head: e/softmax-numerator + GEMM2 accumulation ----------------
    // GEMM2 warp tile 16 rows x 32 cols (8 row-bands x 2 col-bands).
    // Lane grid 4 row-groups x 8 col-groups; lane tile 4x4.
    // Per warp per j: 128B of ht (conflict-free, 1 crossbar cyc) vs 8 FFMA2.
    const int br2  = (wid >> 1) * 16;
    const int bc2  = (wid & 1) * 32;
    const int rg2  = (lane >> 3) * 4;
    const int cg2  = (lane & 7) * 4;
    const int row2 = br2 + rg2;

    ull oacc[4][2];
    #pragma unroll
    for (int r = 0; r < 4; r++) { oacc[r][0] = pack2(0.f, 0.f); oacc[r][1] = pack2(0.f, 0.f); }

    #pragma unroll 1
    for (int h = 0; h < NHEADS; h++) {
        // e-phase: warp w handles rows w*8 .. w*8+7, lanes sweep j
        {
            const float* srch = src_s + h * 128;
            const float* tgth = tgt_s + h * 128;
            #pragma unroll 1
            for (int rr = 0; rr < 8; rr++) {
                const int i = wid * 8 + rr;
                const float si = srch[i];
                float rs = 0.f;
                #pragma unroll
                for (int jj = 0; jj < 4; jj++) {
                    const int j = jj * 32 + lane;
                    float x = si + tgth[j];
                    float u = __expf(-x);
                    float sg = __fdividef(1.0f, 1.0f + u);
                    float p = __expf(sg);
                    if ((maskb[i * 4 + jj] >> lane) & 1u) p = 0.0f;
                    attn[i * 132 + j] = p;
                    rs += p;
                }
                #pragma unroll
                for (int m = 16; m >= 1; m >>= 1)
                    rs += __shfl_xor_sync(0xffffffffu, rs, m);
                if (lane == 0) inv_s[i] = __fdividef(1.0f, rs);
            }
        }
        __syncthreads();

        // GEMM2: th[128][64] = attn[128][128] @ ht[:, h*64:(h+1)*64]
        {
            const int colbase = h * 64 + bc2 + cg2;
            ull th[4][2];
            #pragma unroll
            for (int r = 0; r < 4; r++) { th[r][0] = pack2(0.f, 0.f); th[r][1] = pack2(0.f, 0.f); }

            #pragma unroll 1
            for (int jq = 0; jq < 32; jq++) {
                float4 aq[4];
                #pragma unroll
                for (int r = 0; r < 4; r++)
                    aq[r] = *(const float4*)&attn[(row2 + r) * 132 + jq * 4];
                #pragma unroll
                for (int jj = 0; jj < 4; jj++) {
                    const int j = jq * 4 + jj;
                    ulonglong2 b = *(const ulonglong2*)&ht[j * OCOLS + colbase];
                    #pragma unroll
                    for (int r = 0; r < 4; r++) {
                        float av = ((const float*)&aq[r])[jj];
                        ull a2 = pack2(av, av);
                        fma2(th[r][0], a2, b.x);
                        fma2(th[r][1], a2, b.y);
                    }
                }
            }

            // scale by 1/rowsum and accumulate across heads
            #pragma unroll
            for (int r = 0; r < 4; r++) {
                float iv = inv_s[row2 + r];
                ull iv2 = pack2(iv, iv);
                fma2(oacc[r][0], iv2, th[r][0]);
                fma2(oacc[r][1], iv2, th[r][1]);
            }
        }
        __syncthreads();   // attn/inv_s reused next head
    }

    // ---------------- Write output: mean over heads ----------------
    #pragma unroll
    for (int r = 0; r < 4; r++) {
        float2 p0 = unpack2(oacc[r][0]);
        float2 p1 = unpack2(oacc[r][1]);
        float4 v;
        v.x = p0.x * 0.25f; v.y = p0.y * 0.25f;
        v.z = p1.x * 0.25f; v.w = p1.y * 0.25f;
        *(float4*)&outb[(row2 + r) * NHID + bc2 + cg2] = v;
    }
}

extern "C" void kernel_launch(void* const* d_in, const int* in_sizes, int n_in,
                              void* d_out, int out_size)
{
    const float* h   = (const float*)d_in[0];
    const float* adj = (const float*)d_in[1];
    const float* W   = (const float*)d_in[2];
    const float* a   = (const float*)d_in[3];
    float* out = (float*)d_out;

    static bool attr_set = false;
    if (!attr_set) {
        cudaFuncSetAttribute(gat_fused_kernel,
                             cudaFuncAttributeMaxDynamicSharedMemorySize,
                             SMEM_FLOATS * sizeof(float));
        attr_set = true;
    }

    gat_fused_kernel<<<BATCH_SEQ, THREADS, SMEM_FLOATS * sizeof(float)>>>(h, adj, W, a, out);
}

// round 4
// speedup vs baseline: 1.4769x; 1.4542x over previous
#include <cuda_runtime.h>
#include <cstdint>

// Problem constants
#define BATCH_SEQ 640          // B*S = 32*20
#define NNODE     128
#define FDIM      64
#define NHEADS    4
#define NHID      64
#define OCOLS     256          // NHEADS*NHID
#define THREADS   512
#define ADJ_THR   0.05f

typedef unsigned long long ull;

// ---- packed f32x2 helpers ----
__device__ __forceinline__ void fma2(ull& d, ull a, ull b) {
    asm("fma.rn.f32x2 %0, %1, %2, %0;" : "+l"(d) : "l"(a), "l"(b));
}
__device__ __forceinline__ ull pack2(float x, float y) {
    ull r; asm("mov.b64 %0, {%1, %2};" : "=l"(r) : "f"(x), "f"(y)); return r;
}
__device__ __forceinline__ float2 unpack2(ull v) {
    float2 f; asm("mov.b64 {%0, %1}, %2;" : "=f"(f.x), "=f"(f.y) : "l"(v)); return f;
}
// round-to-nearest tf32 (bit pattern in uint32)
__device__ __forceinline__ uint32_t rna_tf32(float x) {
    uint32_t u; asm("cvt.rna.tf32.f32 %0, %1;" : "=r"(u) : "f"(x)); return u;
}
__device__ __forceinline__ float rcp_approx(float x) {
    float r; asm("rcp.approx.f32 %0, %1;" : "=f"(r) : "f"(x)); return r;
}
// e^y for y in [0,1]: degree-7 Taylor (max rel err ~2.8e-5)
__device__ __forceinline__ float exp01(float y) {
    float p = 1.9841270e-4f;
    p = fmaf(p, y, 1.3888889e-3f);
    p = fmaf(p, y, 8.3333333e-3f);
    p = fmaf(p, y, 4.1666668e-2f);
    p = fmaf(p, y, 1.6666667e-1f);
    p = fmaf(p, y, 0.5f);
    p = fmaf(p, y, 1.0f);
    p = fmaf(p, y, 1.0f);
    return p;
}
// tf32 mma.sync m16n8k8 (baseline PTX, no 'a'-target features needed)
__device__ __forceinline__ void mma_tf32(float c[4],
                                         uint32_t a0, uint32_t a1, uint32_t a2, uint32_t a3,
                                         uint32_t b0, uint32_t b1) {
    asm volatile("mma.sync.aligned.m16n8k8.row.col.f32.tf32.tf32.f32 "
                 "{%0,%1,%2,%3}, {%4,%5,%6,%7}, {%8,%9}, {%0,%1,%2,%3};"
                 : "+f"(c[0]), "+f"(c[1]), "+f"(c[2]), "+f"(c[3])
                 : "r"(a0), "r"(a1), "r"(a2), "r"(a3), "r"(b0), "r"(b1));
}

// Shared memory layout (float index):
//   htt  [4 heads][128 k][stride 73] tf32 bits @ 0          (37376)
//        (also reused as K-split staging area at the end: 12 x 2048 floats)
//   union @ 37376:
//     phase1: W_s [64][256]                                 (16384)
//     phase2: attn [128 i][stride 132] tf32 bits            (16896)
//   src_s [4][128]   @ 54272
//   tgt_s [4][128]   @ 54784
//   maskb [512]u32   @ 55296
#define HTSTRIDE  73
#define HTHEAD    (128 * HTSTRIDE)      // 9344
#define HTT_SIZE  (4 * HTHEAD)          // 37376
#define SCR_OFF   HTT_SIZE
#define ATTSTRIDE 132
#define SRC_OFF   (SCR_OFF + 16896)     // 54272
#define TGT_OFF   (SRC_OFF + 512)
#define MSK_OFF   (TGT_OFF + 512)
#define SMEM_FLOATS (MSK_OFF + 512)     // 55808 floats = 223232 B

extern __shared__ float smem[];

__global__ __launch_bounds__(THREADS, 1)
void gat_fused_kernel(const float* __restrict__ hg,
                      const float* __restrict__ adjg,
                      const float* __restrict__ Wg,
                      const float* __restrict__ ag,
                      float* __restrict__ outg)
{
    float* Ws    = smem + SCR_OFF;
    float* src_s = smem + SRC_OFF;
    float* tgt_s = smem + TGT_OFF;
    unsigned* maskb  = (unsigned*)(smem + MSK_OFF);
    uint32_t* htt_u  = (uint32_t*)smem;
    uint32_t* attn_u = (uint32_t*)(smem + SCR_OFF);

    const int tid  = threadIdx.x;
    const int lane = tid & 31;
    const int wid  = tid >> 5;
    const int bs   = blockIdx.x;

    const float* hb   = hg   + (size_t)bs * NNODE * FDIM;
    const float* adjb = adjg + (size_t)bs * NNODE * NNODE;
    float*       outb = outg + (size_t)bs * NNODE * NHID;

    // ---------------- Load W into smem (coalesced float4) ----------------
    {
        const float4* Wg4 = (const float4*)Wg;
        float4* Ws4 = (float4*)Ws;
        #pragma unroll
        for (int i = 0; i < 8; i++)
            Ws4[tid + i * 512] = Wg4[tid + i * 512];
    }

    // ---------------- Adjacency -> bitmask (bit set == masked) ----------------
    {
        #pragma unroll
        for (int it = 0; it < 32; it++) {
            int idx = it * 512 + tid;
            unsigned bal = __ballot_sync(0xffffffffu, adjb[idx] < ADJ_THR);
            if (lane == 0) maskb[idx >> 5] = bal;
        }
    }
    __syncthreads();

    // ---------------- GEMM1 (SIMT fp32, exact): ht = h @ W ----------------
    // Warp tile 32 rows x 64 cols (col band == head). Lane tile 8x8.
    {
        const int br   = (wid & 3) * 32;
        const int head = wid >> 2;
        const int rg   = (lane >> 3) * 8;
        const int cgi  = lane & 7;
        const int cg   = cgi * 8;
        const int row0 = br + rg;
        const int col0 = head * 64 + cg;

        ull acc[8][4];
        #pragma unroll
        for (int r = 0; r < 8; r++)
            #pragma unroll
            for (int p = 0; p < 4; p++) acc[r][p] = pack2(0.f, 0.f);

        #pragma unroll 1
        for (int kq = 0; kq < 16; kq++) {
            float4 a4[8];
            #pragma unroll
            for (int r = 0; r < 8; r++)
                a4[r] = *(const float4*)&hb[(row0 + r) * FDIM + kq * 4];

            #pragma unroll
            for (int kk = 0; kk < 4; kk++) {
                const int k = kq * 4 + kk;
                const ulonglong2* bp = (const ulonglong2*)&Ws[k * OCOLS + col0];
                ulonglong2 b0 = bp[0];
                ulonglong2 b1 = bp[1];
                #pragma unroll
                for (int r = 0; r < 8; r++) {
                    float av = ((const float*)&a4[r])[kk];
                    ull a2 = pack2(av, av);
                    fma2(acc[r][0], a2, b0.x);
                    fma2(acc[r][1], a2, b0.y);
                    fma2(acc[r][2], a2, b1.x);
                    fma2(acc[r][3], a2, b1.y);
                }
            }
        }

        // Store htt[head][k=row][n=col] tf32-rounded, stride 73.
        // Lane-rotated column order -> conflict-free scalar stores.
        #pragma unroll
        for (int r = 0; r < 8; r++) {
            float a8[8];
            #pragma unroll
            for (int p = 0; p < 4; p++) {
                float2 f = unpack2(acc[r][p]);
                a8[2 * p] = f.x; a8[2 * p + 1] = f.y;
            }
            uint32_t* hrow = htt_u + head * HTHEAD + (row0 + r) * HTSTRIDE + cg;
            #pragma unroll
            for (int s = 0; s < 8; s++) {
                const int cc = (s + cgi) & 7;
                hrow[cc] = rna_tf32(a8[cc]);
            }
        }

        // src/tgt epilogue (full fp32 from register tile)
        float asrc[8], atgt[8];
        #pragma unroll
        for (int j = 0; j < 8; j++) {
            asrc[j] = ag[head * 128 + cg + j];
            atgt[j] = ag[head * 128 + 64 + cg + j];
        }
        #pragma unroll
        for (int r = 0; r < 8; r++) {
            float s = 0.f, t = 0.f;
            #pragma unroll
            for (int p = 0; p < 4; p++) {
                float2 c = unpack2(acc[r][p]);
                s += c.x * asrc[2 * p] + c.y * asrc[2 * p + 1];
                t += c.x * atgt[2 * p] + c.y * atgt[2 * p + 1];
            }
            #pragma unroll
            for (int m = 4; m >= 1; m >>= 1) {
                s += __shfl_xor_sync(0xffffffffu, s, m);
                t += __shfl_xor_sync(0xffffffffu, t, m);
            }
            if (cgi == 0) {
                src_s[head * 128 + row0 + r] = s;
                tgt_s[head * 128 + row0 + r] = t;
            }
        }
    }
    __syncthreads();

    // ---------------- Head loop: e-phase -> HMMA GEMM2 (C accumulated over heads) ----
    // GEMM2 warp mapping: kr = wid>>2 (K-split quarter), quad = wid&3 (2x2 output tile)
    const int kr   = wid >> 2;
    const int quad = wid & 3;
    const int r0   = (quad >> 1) * 64;
    const int c0   = (quad & 1) * 32;
    const int g    = lane >> 2;
    const int t    = lane & 3;

    float C[16][4];
    #pragma unroll
    for (int i = 0; i < 16; i++)
        #pragma unroll
        for (int q = 0; q < 4; q++) C[i][q] = 0.f;

    #pragma unroll 1
    for (int h = 0; h < NHEADS; h++) {
        // ---- e-phase: rows wid*8..wid*8+7, softmax weights normalized + tf32 ----
        {
            const float* srch = src_s + h * 128;
            const float* tgth = tgt_s + h * 128;
            float t4[4];
            #pragma unroll
            for (int jj = 0; jj < 4; jj++) t4[jj] = tgth[jj * 32 + lane];

            #pragma unroll 1
            for (int rr = 0; rr < 8; rr++) {
                const int i = wid * 8 + rr;
                const float si = srch[i];
                float p[4];
                float rs = 0.f;
                #pragma unroll
                for (int jj = 0; jj < 4; jj++) {
                    float x = si + t4[jj];
                    float u = __expf(-x);                  // MUFU 1
                    float sg = rcp_approx(1.0f + u);       // MUFU 2
                    float pv = exp01(sg);                  // FMA poly
                    if ((maskb[i * 4 + jj] >> lane) & 1u) pv = 0.0f;
                    p[jj] = pv;
                    rs += pv;
                }
                #pragma unroll
                for (int m = 16; m >= 1; m >>= 1)
                    rs += __shfl_xor_sync(0xffffffffu, rs, m);
                const float inv = rcp_approx(rs);
                #pragma unroll
                for (int jj = 0; jj < 4; jj++)
                    attn_u[i * ATTSTRIDE + jj * 32 + lane] = rna_tf32(p[jj] * inv);
            }
        }
        __syncthreads();

        // ---- GEMM2 slice: rows [r0,r0+64), cols [c0,c0+32), k in [kr*32, kr*32+32) ----
        {
            const uint32_t* htt_h = htt_u + h * HTHEAD;
            #pragma unroll
            for (int ks = 0; ks < 4; ks++) {
                const int k0 = kr * 32 + ks * 8;
                uint32_t a[4][4];
                #pragma unroll
                for (int mt = 0; mt < 4; mt++) {
                    const uint32_t* ar = attn_u + (r0 + mt * 16 + g) * ATTSTRIDE + k0 + t;
                    a[mt][0] = ar[0];
                    a[mt][1] = ar[8 * ATTSTRIDE];
                    a[mt][2] = ar[4];
                    a[mt][3] = ar[8 * ATTSTRIDE + 4];
                }
                uint32_t b[4][2];
                #pragma unroll
                for (int nt = 0; nt < 4; nt++) {
                    const uint32_t* br_ = htt_h + (k0 + t) * HTSTRIDE + c0 + nt * 8 + g;
                    b[nt][0] = br_[0];
                    b[nt][1] = br_[4 * HTSTRIDE];
                }
                #pragma unroll
                for (int mt = 0; mt < 4; mt++)
                    #pragma unroll
                    for (int nt = 0; nt < 4; nt++)
                        mma_tf32(C[mt * 4 + nt], a[mt][0], a[mt][1], a[mt][2], a[mt][3],
                                 b[nt][0], b[nt][1]);
            }
        }
        __syncthreads();   // attn reused by next head's e-phase
    }

    // ---------------- K-split reduction (staged through dead htt region) ----------------
    float* stage = smem;     // htt region is dead now
    if (kr > 0) {
        float* buf = stage + ((kr - 1) * 4 + quad) * 2048;
        #pragma unroll
        for (int i = 0; i < 16; i++)
            #pragma unroll
            for (int q = 0; q < 4; q++)
                buf[(i * 4 + q) * 32 + lane] = C[i][q];
    }
    __syncthreads();

    if (kr == 0) {
        #pragma unroll
        for (int mt = 0; mt < 4; mt++) {
            #pragma unroll
            for (int nt = 0; nt < 4; nt++) {
                const int ti = mt * 4 + nt;
                #pragma unroll
                for (int pair = 0; pair < 2; pair++) {
                    float v0 = C[ti][pair * 2 + 0];
                    float v1 = C[ti][pair * 2 + 1];
                    #pragma unroll
                    for (int p = 0; p < 3; p++) {
                        const float* buf = stage + (p * 4 + quad) * 2048;
                        v0 += buf[(ti * 4 + pair * 2 + 0) * 32 + lane];
                        v1 += buf[(ti * 4 + pair * 2 + 1) * 32 + lane];
                    }
                    const int row = r0 + mt * 16 + g + 8 * pair;
                    const int col = c0 + nt * 8 + 2 * t;
                    float2 v; v.x = v0 * 0.25f; v.y = v1 * 0.25f;
                    *(float2*)&outb[row * NHID + col] = v;
                }
            }
        }
    }
}

extern "C" void kernel_launch(void* const* d_in, const int* in_sizes, int n_in,
                              void* d_out, int out_size)
{
    const float* h   = (const float*)d_in[0];
    const float* adj = (const float*)d_in[1];
    const float* W   = (const float*)d_in[2];
    const float* a   = (const float*)d_in[3];
    float* out = (float*)d_out;

    static bool attr_set = false;
    if (!attr_set) {
        cudaFuncSetAttribute(gat_fused_kernel,
                             cudaFuncAttributeMaxDynamicSharedMemorySize,
                             SMEM_FLOATS * sizeof(float));
        attr_set = true;
    }

    gat_fused_kernel<<<BATCH_SEQ, THREADS, SMEM_FLOATS * sizeof(float)>>>(h, adj, W, a, out);
}